// round 17
// baseline (speedup 1.0000x reference)
#include <cuda_runtime.h>
#include <cuda.h>
#include <cuda_bf16.h>
#include <cstdint>
#include <math.h>

#define NB    2048
#define DD    16
#define EE    256
#define HH    768
#define G3    2304
#define TT    8
#define NPRED 12
#define SCALEF 4.0f

#if defined(__CUDA_ARCH_FEAT_SM103_ALL) || defined(__CUDA_ARCH_FEAT_SM100_ALL) || \
    (defined(__CUDA_ARCH_SPECIFIC__) && (__CUDA_ARCH_SPECIFIC__ >= 1000))
#define HAS_TCG 1
#else
#define HAS_TCG 0
#endif

// ---------------- device scratch ----------------
__device__ __align__(256) float g_M1[G3*DD];
__device__ __align__(256) float g_M2[G3*DD];
__device__ __align__(256) float g_Md[G3*DD];
__device__ __align__(256) float g_b1[G3];
__device__ __align__(256) float g_b2[G3];
__device__ __align__(256) float g_bd[G3];
__device__ __align__(256) __nv_bfloat16 g_Bh1[G3*HH];
__device__ __align__(256) __nv_bfloat16 g_Bl1[G3*HH];
__device__ __align__(256) __nv_bfloat16 g_Bh2[G3*HH];
__device__ __align__(256) __nv_bfloat16 g_Bl2[G3*HH];
__device__ __align__(256) __nv_bfloat16 g_Bhd[G3*HH];
__device__ __align__(256) __nv_bfloat16 g_Bld[G3*HH];
__device__ __align__(256) __nv_bfloat16 g_Bh2x[G3*HH];
__device__ __align__(256) __nv_bfloat16 g_Bl2x[G3*HH];
__device__ __align__(256) __nv_bfloat16 g_Ah[NB*HH];
__device__ __align__(256) __nv_bfloat16 g_Al[NB*HH];
__device__ __align__(256) float g_C2[NB*G3];
__device__ __align__(256) float g_G[NB*G3];
__device__ __align__(256) float g_h[NB*HH];

// ---------------- helpers ----------------
__device__ __forceinline__ uint32_t smem_u32(const void* p) {
    uint32_t a;
    asm("{ .reg .u64 t; cvta.to.shared.u64 t, %1; cvt.u32.u64 %0, t; }" : "=r"(a) : "l"(p));
    return a;
}
__device__ __forceinline__ uint32_t elect_one() {
    uint32_t pred;
    asm volatile("{\n\t.reg .pred p;\n\telect.sync _|p, 0xFFFFFFFF;\n\t"
                 "selp.b32 %0, 1, 0, p;\n\t}" : "=r"(pred));
    return pred;
}
__device__ __forceinline__ uint32_t ctarank() {
    uint32_t r;
    asm("mov.u32 %0, %%cluster_ctarank;" : "=r"(r));
    return r;
}
__device__ __forceinline__ void mbar_init(uint32_t m, uint32_t c) {
    asm volatile("mbarrier.init.shared.b64 [%0], %1;" :: "r"(m), "r"(c) : "memory");
}
__device__ __forceinline__ void mbar_inval(uint32_t m) {
    asm volatile("mbarrier.inval.shared.b64 [%0];" :: "r"(m) : "memory");
}
__device__ __forceinline__ void mbar_wait(uint32_t m, uint32_t par) {
    uint32_t done;
    asm volatile("{\n\t.reg .pred p;\n\t"
        "mbarrier.try_wait.parity.acquire.cta.shared::cta.b64 p, [%1], %2;\n\t"
        "selp.b32 %0, 1, 0, p;\n\t}" : "=r"(done) : "r"(m), "r"(par) : "memory");
    while (!done) {
        asm volatile("{\n\t.reg .pred p;\n\t"
            "mbarrier.try_wait.parity.acquire.cta.shared::cta.b64 p, [%1], %2, 0x989680;\n\t"
            "selp.b32 %0, 1, 0, p;\n\t}" : "=r"(done) : "r"(m), "r"(par) : "memory");
    }
}
#define CLUSTER_SYNC() do { \
    asm volatile("barrier.cluster.arrive.aligned;" ::: "memory"); \
    asm volatile("barrier.cluster.wait.aligned;" ::: "memory"); \
} while (0)

#if HAS_TCG
#define TC_ALLOC(s, n)   asm volatile("tcgen05.alloc.cta_group::1.sync.aligned.shared::cta.b32 [%0], %1;" :: "r"(s), "r"((uint32_t)(n)) : "memory")
#define TC_DEALLOC(t, n) asm volatile("tcgen05.dealloc.cta_group::1.sync.aligned.b32 %0, %1;" :: "r"(t), "r"((uint32_t)(n)))
#define TC_RELINQUISH()  asm volatile("tcgen05.relinquish_alloc_permit.cta_group::1.sync.aligned;")
// multicast commit: MMA completion arrives on the same-offset empty bar in both CTAs
#define TC_COMMIT_MC(m) \
    asm volatile("tcgen05.commit.cta_group::1.mbarrier::arrive::one.shared::cluster.multicast::cluster.b64 [%0], %1;" \
        :: "r"(m), "h"((uint16_t)0x3) : "memory")
#define TC_FENCE_AFTER()  asm volatile("tcgen05.fence::after_thread_sync;" ::: "memory")
#define TC_FENCE_BEFORE() asm volatile("tcgen05.fence::before_thread_sync;" ::: "memory")
#define TC_WAIT_LD()      asm volatile("tcgen05.wait::ld.sync.aligned;" ::: "memory")

#define TC_LD_X32(r, addr) \
    asm volatile("tcgen05.ld.sync.aligned.32x32b.x32.b32 " \
        "{%0, %1, %2, %3, %4, %5, %6, %7, " \
        " %8, %9, %10, %11, %12, %13, %14, %15, " \
        " %16, %17, %18, %19, %20, %21, %22, %23, " \
        " %24, %25, %26, %27, %28, %29, %30, %31}, [%32];" \
        : "=r"((r)[0]),  "=r"((r)[1]),  "=r"((r)[2]),  "=r"((r)[3]), \
          "=r"((r)[4]),  "=r"((r)[5]),  "=r"((r)[6]),  "=r"((r)[7]), \
          "=r"((r)[8]),  "=r"((r)[9]),  "=r"((r)[10]), "=r"((r)[11]), \
          "=r"((r)[12]), "=r"((r)[13]), "=r"((r)[14]), "=r"((r)[15]), \
          "=r"((r)[16]), "=r"((r)[17]), "=r"((r)[18]), "=r"((r)[19]), \
          "=r"((r)[20]), "=r"((r)[21]), "=r"((r)[22]), "=r"((r)[23]), \
          "=r"((r)[24]), "=r"((r)[25]), "=r"((r)[26]), "=r"((r)[27]), \
          "=r"((r)[28]), "=r"((r)[29]), "=r"((r)[30]), "=r"((r)[31]) \
        : "r"(addr))

__device__ __forceinline__ void mma_bf16_ss(uint32_t d, uint64_t ad, uint64_t bd,
                                            uint32_t idesc, uint32_t en) {
    asm volatile("{\n\t.reg .pred p;\n\tsetp.ne.u32 p, %5, 0;\n\t"
        "tcgen05.mma.cta_group::1.kind::f16 [%0], %1, %2, %3, {%4, %4, %4, %4}, p;\n\t}"
        :: "r"(d), "l"(ad), "l"(bd), "r"(idesc), "r"(0u), "r"(en) : "memory");
}
#define MMA_IDESC ((1u<<4) | (1u<<7) | (1u<<10) | ((128u/8u)<<17) | ((128u/16u)<<24))

__device__ __forceinline__ uint64_t make_desc_sw128(uint32_t addr) {
    const uint64_t base =
        (uint64_t(2) << 61) | (uint64_t(1) << 46) | (uint64_t(64) << 32) | (uint64_t(1) << 16);
    return base | ((uint64_t)(addr >> 4) & 0x3FFF);
}

#define MBAR_EXPECT_TX(m, bytes) \
    asm volatile("mbarrier.arrive.expect_tx.shared.b64 _, [%0], %1;" \
                 :: "r"(m), "r"((uint32_t)(bytes)) : "memory")
#define TMA_LD_2D(dst, map, x, y, mbar) \
    asm volatile("cp.async.bulk.tensor.2d.shared::cta.global.tile.mbarrier::complete_tx::bytes " \
                 "[%0], [%1, {%2, %3}], [%4];" \
                 :: "r"(dst), "l"(map), "r"(x), "r"(y), "r"(mbar) : "memory")
#define TMA_LD_2D_MC(dst, map, x, y, mbar) \
    asm volatile("cp.async.bulk.tensor.2d.shared::cluster.global.tile.mbarrier::complete_tx::bytes.multicast::cluster " \
                 "[%0], [%1, {%2, %3}], [%4], %5;" \
                 :: "r"(dst), "l"(map), "r"(x), "r"(y), "r"(mbar), "h"((uint16_t)0x3) : "memory")
#endif

// ---------------- GEMM: C(2048x2304) = A(2048x768) @ B(2304x768)^T -----------
// KC=64, SW128, 2 stages, warp-specialized producer/consumer.
// Cluster (1,2): row-pair CTAs share B; each rank multicasts its half of B.
#define KC      64
#define NCHUNK  (HH / KC)             // 12
#define TILEB   16384                 // 128 rows x 128B
#define STAGEB  (6 * TILEB)
#define GEMM_SMEM (1024 + 2 * STAGEB) // 197632

__global__ void __launch_bounds__(256, 1) __cluster_dims__(1, 2, 1)
gemm_tc(const __grid_constant__ CUtensorMap mAh, const __grid_constant__ CUtensorMap mAl,
        const __grid_constant__ CUtensorMap mBh, const __grid_constant__ CUtensorMap mBl,
        const __nv_bfloat16* __restrict__ Ahg, const __nv_bfloat16* __restrict__ Alg,
        const __nv_bfloat16* __restrict__ Bhg, const __nv_bfloat16* __restrict__ Blg,
        float* __restrict__ C) {
    extern __shared__ char smem[];
    int tid = threadIdx.x, wid = tid >> 5, lane = tid & 31;
#if HAS_TCG
    uint32_t sb = smem_u32(smem);
    uint32_t rank = ctarank();
    // full: sb+16, sb+24 (count 1, tx-gated); empty: sb+32, sb+40 (count 2: both consumers)
    if (wid == 0) TC_ALLOC(sb, 512);
    if (tid == 0) {
        mbar_init(sb+16,1); mbar_init(sb+24,1);
        mbar_init(sb+32,2); mbar_init(sb+40,2);
    }
    __syncthreads();
    CLUSTER_SYNC();   // barriers visible before any multicast targets them
    uint32_t tmem;
    asm volatile("ld.shared.b32 %0, [%1];" : "=r"(tmem) : "r"(sb));

    int arow = blockIdx.y * 128;
    int brow = blockIdx.x * 256;

    if (wid == 1 && elect_one()) {
        // -------- producer: local A + multicast half-B --------
        for (int i = 0; i < NCHUNK; i++) {
            int slot = i & 1;
            uint32_t stgu = sb + 1024 + slot * STAGEB;
            uint32_t fb = sb + 16 + 8 * slot;
            if (i >= 2) mbar_wait(sb + 32 + 8 * slot, ((i - 2) >> 1) & 1);
            MBAR_EXPECT_TX(fb, 6 * TILEB);
            int kc0 = i * KC;
            TMA_LD_2D(stgu,           &mAh, kc0, arow, fb);
            TMA_LD_2D(stgu + TILEB,   &mAl, kc0, arow, fb);
            // rank r loads B rows [brow + r*128, +128) into offset (2 + 2r)*TILEB,
            // multicast to both CTAs (each CTA ends with the full 4 B tiles)
            uint32_t bo = stgu + (2 + 2 * rank) * TILEB;
            TMA_LD_2D_MC(bo,         &mBh, kc0, brow + (int)rank * 128, fb);
            TMA_LD_2D_MC(bo + TILEB, &mBl, kc0, brow + (int)rank * 128, fb);
        }
    } else if (wid == 0 && elect_one()) {
        // -------- consumer: MMA; commit multicast to BOTH empty bars --------
        for (int i = 0; i < NCHUNK; i++) {
            int slot = i & 1;
            uint32_t stgu = sb + 1024 + slot * STAGEB;
            mbar_wait(sb + 16 + 8 * slot, (i >> 1) & 1);

            uint64_t dAh  = make_desc_sw128(stgu);
            uint64_t dAl  = make_desc_sw128(stgu + TILEB);
            uint64_t dBh0 = make_desc_sw128(stgu + 2*TILEB);
            uint64_t dBl0 = make_desc_sw128(stgu + 3*TILEB);
            uint64_t dBh1 = make_desc_sw128(stgu + 4*TILEB);
            uint64_t dBl1 = make_desc_sw128(stgu + 5*TILEB);
            uint32_t first = (i == 0) ? 0u : 1u;
            #pragma unroll
            for (int s = 0; s < 4; s++) {
                uint64_t o = (uint64_t)(s * 2);
                uint32_t en0 = (s == 0) ? first : 1u;
                mma_bf16_ss(tmem,       dAh + o, dBh0 + o, MMA_IDESC, en0);
                mma_bf16_ss(tmem,       dAh + o, dBl0 + o, MMA_IDESC, 1u);
                mma_bf16_ss(tmem,       dAl + o, dBh0 + o, MMA_IDESC, 1u);
                mma_bf16_ss(tmem + 128, dAh + o, dBh1 + o, MMA_IDESC, en0);
                mma_bf16_ss(tmem + 128, dAh + o, dBl1 + o, MMA_IDESC, 1u);
                mma_bf16_ss(tmem + 128, dAl + o, dBh1 + o, MMA_IDESC, 1u);
            }
            TC_COMMIT_MC(sb + 32 + 8 * slot);
        }
        // drain: per slot, 6 flips (12 arrivals at count 2); loop consumed 0..4 -> parity 1
        mbar_wait(sb + 32, 1);
        mbar_wait(sb + 40, 1);
    }
    __syncthreads();
    TC_FENCE_AFTER();

    int sub = wid & 3, half = wid >> 2;
    int rowg = blockIdx.y * 128 + sub * 32 + lane;
    float* crow = C + (size_t)rowg * G3 + blockIdx.x * 256 + half * 128;
    #pragma unroll
    for (int part = 0; part < 2; part++) {
        uint32_t r0[32], r1[32];
        TC_LD_X32(r0, tmem + half * 128 + part * 64);
        TC_LD_X32(r1, tmem + half * 128 + part * 64 + 32);
        TC_WAIT_LD();
        #pragma unroll
        for (int c = 0; c < 32; c += 4) {
            *(float4*)(crow + part*64 + c) = make_float4(
                __uint_as_float(r0[c]),   __uint_as_float(r0[c+1]),
                __uint_as_float(r0[c+2]), __uint_as_float(r0[c+3]));
            *(float4*)(crow + part*64 + 32 + c) = make_float4(
                __uint_as_float(r1[c]),   __uint_as_float(r1[c+1]),
                __uint_as_float(r1[c+2]), __uint_as_float(r1[c+3]));
        }
    }
    TC_FENCE_BEFORE();
    __syncthreads();
    if (tid == 0) {
        mbar_inval(sb+16); mbar_inval(sb+24);
        mbar_inval(sb+32); mbar_inval(sb+40);
    }
    __syncthreads();
    if (wid == 0) { TC_RELINQUISH(); TC_DEALLOC(tmem, 512); }
    CLUSTER_SYNC();   // no CTA exits while peer multicast may be in flight
#else
    // FFMA fallback (plain sm_103 pass only; never selected at runtime on GB300)
    float* As = (float*)smem;
    float* Bs = As + 16 * 128;
    int ty = tid >> 4, tx = tid & 15;
    const __nv_bfloat16* Ahb = Ahg + (size_t)blockIdx.y * 128 * HH;
    const __nv_bfloat16* Alb = Alg + (size_t)blockIdx.y * 128 * HH;
    for (int nb = 0; nb < 2; nb++) {
        const __nv_bfloat16* Bhb = Bhg + (size_t)(blockIdx.x * 256 + nb * 128) * HH;
        const __nv_bfloat16* Blb = Blg + (size_t)(blockIdx.x * 256 + nb * 128) * HH;
        float acc[8][8];
        #pragma unroll
        for (int i = 0; i < 8; i++)
            #pragma unroll
            for (int j = 0; j < 8; j++) acc[i][j] = 0.0f;
        for (int kt = 0; kt < HH; kt += 16) {
            {
                int r = tid >> 1, kq = (tid & 1) * 8;
                size_t go = (size_t)r * HH + kt + kq;
                uint4 vh = *(const uint4*)(Ahb + go);
                uint4 vl = *(const uint4*)(Alb + go);
                const __nv_bfloat16* ph = (const __nv_bfloat16*)&vh;
                const __nv_bfloat16* pl = (const __nv_bfloat16*)&vl;
                #pragma unroll
                for (int e = 0; e < 8; e++)
                    As[(kq + e) * 128 + r] = __bfloat162float(ph[e]) + __bfloat162float(pl[e]);
            }
            {
                int n = tid >> 1, kq = (tid & 1) * 8;
                size_t go = (size_t)n * HH + kt + kq;
                uint4 vh = *(const uint4*)(Bhb + go);
                uint4 vl = *(const uint4*)(Blb + go);
                const __nv_bfloat16* ph = (const __nv_bfloat16*)&vh;
                const __nv_bfloat16* pl = (const __nv_bfloat16*)&vl;
                #pragma unroll
                for (int e = 0; e < 8; e++)
                    Bs[(kq + e) * 128 + n] = __bfloat162float(ph[e]) + __bfloat162float(pl[e]);
            }
            __syncthreads();
            #pragma unroll
            for (int k = 0; k < 16; k++) {
                float ar[8], br[8];
                #pragma unroll
                for (int e = 0; e < 8; e++) ar[e] = As[k * 128 + ty * 8 + e];
                #pragma unroll
                for (int e = 0; e < 8; e++) br[e] = Bs[k * 128 + tx * 8 + e];
                #pragma unroll
                for (int i = 0; i < 8; i++)
                    #pragma unroll
                    for (int j = 0; j < 8; j++)
                        acc[i][j] = fmaf(ar[i], br[j], acc[i][j]);
            }
            __syncthreads();
        }
        int rowBase = blockIdx.y * 128 + ty * 8;
        int colBase = blockIdx.x * 256 + nb * 128 + tx * 8;
        #pragma unroll
        for (int i = 0; i < 8; i++) {
            *(float4*)(C + (size_t)(rowBase + i) * G3 + colBase) =
                make_float4(acc[i][0], acc[i][1], acc[i][2], acc[i][3]);
            *(float4*)(C + (size_t)(rowBase + i) * G3 + colBase + 4) =
                make_float4(acc[i][4], acc[i][5], acc[i][6], acc[i][7]);
        }
        __syncthreads();
    }
#endif
}

// ---------------- batched prep kernels ----------------
__global__ void conv_all(const float* __restrict__ W1, const float* __restrict__ W2,
                         const float* __restrict__ Wd, const float* __restrict__ W2x,
                         __nv_bfloat16* __restrict__ h1, __nv_bfloat16* __restrict__ l1,
                         __nv_bfloat16* __restrict__ h2, __nv_bfloat16* __restrict__ l2,
                         __nv_bfloat16* __restrict__ hd, __nv_bfloat16* __restrict__ ld,
                         __nv_bfloat16* __restrict__ h2x, __nv_bfloat16* __restrict__ l2x) {
    int idx = blockIdx.x * blockDim.x + threadIdx.x;
    const int WN = G3 * HH;
    if (idx >= 4 * WN) return;
    int w = idx / WN, r = idx % WN;
    int j = r / HH, k = r % HH;
    float x;
    __nv_bfloat16 *hi, *lo;
    if (w == 0)      { x = W1[(size_t)j * HH + k];              hi = h1;  lo = l1; }
    else if (w == 1) { x = W2[(size_t)j * HH + k];              hi = h2;  lo = l2; }
    else if (w == 2) { x = Wd[(size_t)j * HH + k];              hi = hd;  lo = ld; }
    else             { x = W2x[(size_t)j * (EE + HH) + EE + k]; hi = h2x; lo = l2x; }
    __nv_bfloat16 h = __float2bfloat16(x);
    hi[r] = h;
    lo[r] = __float2bfloat16(x - __bfloat162float(h));
}

__global__ void prep_all(const float* __restrict__ W1, const float* __restrict__ W2,
                         const float* __restrict__ Wd,
                         const float* __restrict__ b1i, const float* __restrict__ b2i,
                         const float* __restrict__ bdi,
                         const float* __restrict__ embW, const float* __restrict__ embB,
                         float* __restrict__ M1, float* __restrict__ M2, float* __restrict__ Md,
                         float* __restrict__ b1o, float* __restrict__ b2o, float* __restrict__ bdo) {
    int idx = blockIdx.x * blockDim.x + threadIdx.x;
    const int WN = G3 * 4;
    if (idx >= 3 * WN) return;
    int w = idx / WN, r = idx % WN;
    int p = r >> 2, q = r & 3;
    const float* wrow;
    const float* bin;
    float *MT, *bout;
    if (w == 0)      { wrow = W1 + (size_t)p * EE;        bin = b1i; MT = M1; bout = b1o; }
    else if (w == 1) { wrow = W2 + (size_t)p * (EE + HH); bin = b2i; MT = M2; bout = b2o; }
    else             { wrow = Wd + (size_t)p * EE;        bin = bdi; MT = Md; bout = bdo; }
    float accM[4] = {0.f, 0.f, 0.f, 0.f};
    float accb = 0.0f;
    for (int e = 0; e < EE; e++) {
        float ww = wrow[e];
        const float* er = embW + e * DD + q * 4;
        accM[0] = fmaf(er[0], ww, accM[0]);
        accM[1] = fmaf(er[1], ww, accM[1]);
        accM[2] = fmaf(er[2], ww, accM[2]);
        accM[3] = fmaf(er[3], ww, accM[3]);
        if (q == 0) accb = fmaf(embB[e], ww, accb);
    }
    *(float4*)(MT + (size_t)p * DD + q * 4) =
        make_float4(SCALEF*accM[0], SCALEF*accM[1], SCALEF*accM[2], SCALEF*accM[3]);
    if (q == 0) bout[p] = accb + bin[p];
}

// ---------------- GRU update: 8-row batch, MT coalesced, grid (3,256) -------
#define GRU_ROWS 8
__global__ void __launch_bounds__(256)
gru_update(const float* __restrict__ MT, const float* __restrict__ bvec,
           const float* __restrict__ bhh, const float* __restrict__ C2,
           const float* __restrict__ G,
           const float* __restrict__ pa, const float* __restrict__ pb,
           float* __restrict__ h,
           __nv_bfloat16* __restrict__ ah, __nv_bfloat16* __restrict__ al) {
    int tid = threadIdx.x;
    int j = blockIdx.x * 256 + tid;
    int row0 = blockIdx.y * GRU_ROWS;

    __shared__ float sv[GRU_ROWS][DD];
    if (tid < GRU_ROWS * DD) {
        int r = tid >> 4, d = tid & 15;
        sv[r][d] = pa[(size_t)(row0 + r) * DD + d] - pb[(size_t)(row0 + r) * DD + d];
    }
    __syncthreads();

    float4 m[3][4];
    #pragma unroll
    for (int g = 0; g < 3; g++)
        #pragma unroll
        for (int q = 0; q < 4; q++)
            m[g][q] = *(const float4*)(MT + (size_t)(g * HH + j) * DD + q * 4);

    float bvr = bvec[j], bvz = bvec[j + HH], bvn = bvec[j + 2 * HH];
    float bhr = bhh[j],  bhz = bhh[j + HH],  bhn = bhh[j + 2 * HH];

    #pragma unroll
    for (int r = 0; r < GRU_ROWS; r++) {
        int row = row0 + r;
        size_t idx = (size_t)row * HH + j;
        float gi_r = bvr, gi_z = bvz, gi_n = bvn;
        #pragma unroll
        for (int q = 0; q < 4; q++) {
            float v0 = sv[r][q*4], v1 = sv[r][q*4+1], v2 = sv[r][q*4+2], v3 = sv[r][q*4+3];
            gi_r = fmaf(v0, m[0][q].x, fmaf(v1, m[0][q].y, fmaf(v2, m[0][q].z, fmaf(v3, m[0][q].w, gi_r))));
            gi_z = fmaf(v0, m[1][q].x, fmaf(v1, m[1][q].y, fmaf(v2, m[1][q].z, fmaf(v3, m[1][q].w, gi_z))));
            gi_n = fmaf(v0, m[2][q].x, fmaf(v1, m[2][q].y, fmaf(v2, m[2][q].z, fmaf(v3, m[2][q].w, gi_n))));
        }
        if (C2 != nullptr) {
            const float* c = C2 + (size_t)row * G3;
            gi_r += c[j];
            gi_z += c[j + HH];
            gi_n += c[j + 2 * HH];
        }
        float gh_r = bhr, gh_z = bhz, gh_n = bhn;
        float ho = 0.0f;
        if (G != nullptr) {
            const float* grow = G + (size_t)row * G3;
            gh_r += grow[j];
            gh_z += grow[j + HH];
            gh_n += grow[j + 2 * HH];
            ho = h[idx];
        }
        float rr = 1.0f / (1.0f + expf(-(gi_r + gh_r)));
        float zz = 1.0f / (1.0f + expf(-(gi_z + gh_z)));
        float nn = tanhf(gi_n + rr * gh_n);
        float hn = (1.0f - zz) * nn + zz * ho;
        h[idx] = hn;
        __nv_bfloat16 hb = __float2bfloat16(hn);
        ah[idx] = hb;
        al[idx] = __float2bfloat16(hn - __bfloat162float(hb));
    }
}

// ---------------- decoder head: one warp per row, h read once ---------------
__global__ void __launch_bounds__(256)
h2n_pos(const float* __restrict__ h,
        const float* __restrict__ h2nW, const float* __restrict__ h2nB,
        const float* __restrict__ mixW, const float* __restrict__ mixB,
        const float* __restrict__ base,
        float* __restrict__ out_rel, float* __restrict__ out_pos) {
    int w = threadIdx.x >> 5, lane = threadIdx.x & 31;
    int row = blockIdx.x * 8 + w;

    const float* hr = h + (size_t)row * HH;
    float s0 = 0.f, s1 = 0.f, s2 = 0.f, s3 = 0.f, s4 = 0.f;
    for (int i = lane; i < HH; i += 32) {
        float hv = hr[i];
        s0 = fmaf(hv, h2nW[i],          s0);
        s1 = fmaf(hv, h2nW[HH + i],     s1);
        s2 = fmaf(hv, h2nW[2*HH + i],   s2);
        s3 = fmaf(hv, h2nW[3*HH + i],   s3);
        s4 = fmaf(hv, h2nW[4*HH + i],   s4);
    }
    #pragma unroll
    for (int o = 16; o > 0; o >>= 1) {
        s0 += __shfl_down_sync(0xffffffffu, s0, o);
        s1 += __shfl_down_sync(0xffffffffu, s1, o);
        s2 += __shfl_down_sync(0xffffffffu, s2, o);
        s3 += __shfl_down_sync(0xffffffffu, s3, o);
        s4 += __shfl_down_sync(0xffffffffu, s4, o);
    }
    float v0, v1, v2, v3, v4;
    if (lane == 0) {
        v0 = s0 + h2nB[0];
        v1 = s1 + h2nB[1];
        float r2 = s2 + h2nB[2];
        float r3 = s3 + h2nB[3];
        float r4 = s4 + h2nB[4];
        float sp2 = r2 > 0.0f ? r2 + log1pf(expf(-r2)) : log1pf(expf(r2));
        float sp3 = r3 > 0.0f ? r3 + log1pf(expf(-r3)) : log1pf(expf(r3));
        v2 = 0.01f + 0.2f * sp2;
        v3 = 0.01f + 0.2f * sp3;
        v4 = 0.7f * tanhf(r4);
        float* ro = out_rel + (size_t)row * 5;
        ro[0] = v0; ro[1] = v1; ro[2] = v2; ro[3] = v3; ro[4] = v4;
    }
    v0 = __shfl_sync(0xffffffffu, v0, 0);
    v1 = __shfl_sync(0xffffffffu, v1, 0);
    v2 = __shfl_sync(0xffffffffu, v2, 0);
    v3 = __shfl_sync(0xffffffffu, v3, 0);
    v4 = __shfl_sync(0xffffffffu, v4, 0);
    if (lane < DD) {
        float acc = mixB[lane];
        const float* mw = mixW + lane * 5;
        acc = fmaf(v0, mw[0], acc);
        acc = fmaf(v1, mw[1], acc);
        acc = fmaf(v2, mw[2], acc);
        acc = fmaf(v3, mw[3], acc);
        acc = fmaf(v4, mw[4], acc);
        acc = acc > 0.0f ? acc : 0.0f;
        out_pos[(size_t)row * DD + lane] = base[(size_t)row * DD + lane] + acc;
    }
}

// ---------------- host: tensor-map creation ----------------
typedef CUresult (*PFN_tmEncode)(CUtensorMap*, CUtensorMapDataType, cuuint32_t, void*,
                                 const cuuint64_t*, const cuuint64_t*, const cuuint32_t*,
                                 const cuuint32_t*, CUtensorMapInterleave, CUtensorMapSwizzle,
                                 CUtensorMapL2promotion, CUtensorMapFloatOOBfill);

static PFN_tmEncode tm_encode_fn() {
    static PFN_tmEncode fn = nullptr;
    if (!fn) {
        void* p = nullptr;
        cudaDriverEntryPointQueryResult qr;
        cudaGetDriverEntryPoint("cuTensorMapEncodeTiled", &p, cudaEnableDefault, &qr);
        fn = (PFN_tmEncode)p;
    }
    return fn;
}

static void make_map_bf16(CUtensorMap* m, void* ptr, int rows) {
    cuuint64_t dims[2]    = {(cuuint64_t)HH, (cuuint64_t)rows};
    cuuint64_t strides[1] = {(cuuint64_t)HH * 2};
    cuuint32_t box[2]     = {64, 128};
    cuuint32_t es[2]      = {1, 1};
    tm_encode_fn()(m, CU_TENSOR_MAP_DATA_TYPE_BFLOAT16, 2, ptr, dims, strides, box, es,
                   CU_TENSOR_MAP_INTERLEAVE_NONE, CU_TENSOR_MAP_SWIZZLE_128B,
                   CU_TENSOR_MAP_L2_PROMOTION_L2_128B, CU_TENSOR_MAP_FLOAT_OOB_FILL_NONE);
}

// ---------------- host orchestration ----------------
extern "C" void kernel_launch(void* const* d_in, const int* in_sizes, int n_in,
                              void* d_out, int out_size) {
    const float* observed = (const float*)d_in[0];
    const float* emb_W    = (const float*)d_in[1];
    const float* emb_b    = (const float*)d_in[2];
    const float* e1_Wih   = (const float*)d_in[3];
    const float* e1_Whh   = (const float*)d_in[4];
    const float* e1_bih   = (const float*)d_in[5];
    const float* e1_bhh   = (const float*)d_in[6];
    const float* e2_Wih   = (const float*)d_in[7];
    const float* e2_Whh   = (const float*)d_in[8];
    const float* e2_bih   = (const float*)d_in[9];
    const float* e2_bhh   = (const float*)d_in[10];
    const float* dec_Wih  = (const float*)d_in[11];
    const float* dec_Whh  = (const float*)d_in[12];
    const float* dec_bih  = (const float*)d_in[13];
    const float* dec_bhh  = (const float*)d_in[14];
    const float* h2n_W    = (const float*)d_in[15];
    const float* h2n_b    = (const float*)d_in[16];
    const float* mix_W    = (const float*)d_in[17];
    const float* mix_b    = (const float*)d_in[18];
    float* out = (float*)d_out;

    float *M1, *M2, *Md, *b1, *b2, *bd, *C2, *G, *h;
    __nv_bfloat16 *Bh1, *Bl1, *Bh2, *Bl2, *Bhd, *Bld, *Bh2x, *Bl2x, *Ah, *Al;
    cudaGetSymbolAddress((void**)&M1,  g_M1);
    cudaGetSymbolAddress((void**)&M2,  g_M2);
    cudaGetSymbolAddress((void**)&Md,  g_Md);
    cudaGetSymbolAddress((void**)&b1,  g_b1);
    cudaGetSymbolAddress((void**)&b2,  g_b2);
    cudaGetSymbolAddress((void**)&bd,  g_bd);
    cudaGetSymbolAddress((void**)&Bh1, g_Bh1);
    cudaGetSymbolAddress((void**)&Bl1, g_Bl1);
    cudaGetSymbolAddress((void**)&Bh2, g_Bh2);
    cudaGetSymbolAddress((void**)&Bl2, g_Bl2);
    cudaGetSymbolAddress((void**)&Bhd, g_Bhd);
    cudaGetSymbolAddress((void**)&Bld, g_Bld);
    cudaGetSymbolAddress((void**)&Bh2x,g_Bh2x);
    cudaGetSymbolAddress((void**)&Bl2x,g_Bl2x);
    cudaGetSymbolAddress((void**)&Ah,  g_Ah);
    cudaGetSymbolAddress((void**)&Al,  g_Al);
    cudaGetSymbolAddress((void**)&C2,  g_C2);
    cudaGetSymbolAddress((void**)&G,   g_G);
    cudaGetSymbolAddress((void**)&h,   g_h);

    CUtensorMap tAh, tAl, tB1h, tB1l, tB2h, tB2l, tBdh, tBdl, tB2xh, tB2xl;
    make_map_bf16(&tAh,  Ah,  NB);
    make_map_bf16(&tAl,  Al,  NB);
    make_map_bf16(&tB1h, Bh1, G3);
    make_map_bf16(&tB1l, Bl1, G3);
    make_map_bf16(&tB2h, Bh2, G3);
    make_map_bf16(&tB2l, Bl2, G3);
    make_map_bf16(&tBdh, Bhd, G3);
    make_map_bf16(&tBdl, Bld, G3);
    make_map_bf16(&tB2xh, Bh2x, G3);
    make_map_bf16(&tB2xl, Bl2x, G3);

    cudaFuncSetAttribute(gemm_tc, cudaFuncAttributeMaxDynamicSharedMemorySize, GEMM_SMEM);

    const int ND = NB * DD;
    float* rel_out  = out;
    float* pred_out = out + (size_t)NPRED * NB * 5;

    dim3 gemmGrid(G3 / 256, NB / 128);        // (9,16); clusters pair along y
    dim3 gruGrid(HH / 256, NB / GRU_ROWS);    // (3,256)

    conv_all<<<(4 * G3 * HH + 255) / 256, 256>>>(
        e1_Whh, e2_Whh, dec_Whh, e2_Wih,
        Bh1, Bl1, Bh2, Bl2, Bhd, Bld, Bh2x, Bl2x);
    prep_all<<<(3 * G3 * 4 + 255) / 256, 256>>>(
        e1_Wih, e2_Wih, dec_Wih, e1_bih, e2_bih, dec_bih,
        emb_W, emb_b, M1, M2, Md, b1, b2, bd);

    // ---- encoder 1 (backward velocities) ----
    for (int t = 0; t < TT - 1; t++) {
        const float* pa = observed + (size_t)(7 - t) * ND;
        const float* pb = observed + (size_t)(6 - t) * ND;
        const float* Gp = nullptr;
        if (t > 0) {
            gemm_tc<<<gemmGrid, 256, GEMM_SMEM>>>(tAh, tAl, tB1h, tB1l, Ah, Al, Bh1, Bl1, G);
            Gp = G;
        }
        gru_update<<<gruGrid, 256>>>(M1, b1, e1_bhh, nullptr, Gp, pa, pb, h, Ah, Al);
    }

    // C2 = h_inv @ e2_Wih[:,256:]^T
    gemm_tc<<<gemmGrid, 256, GEMM_SMEM>>>(tAh, tAl, tB2xh, tB2xl, Ah, Al, Bh2x, Bl2x, C2);

    // ---- encoder 2 (forward velocities) ----
    for (int t = 0; t < TT - 1; t++) {
        const float* pa = observed + (size_t)(t + 1) * ND;
        const float* pb = observed + (size_t)t * ND;
        const float* Gp = nullptr;
        if (t > 0) {
            gemm_tc<<<gemmGrid, 256, GEMM_SMEM>>>(tAh, tAl, tB2h, tB2l, Ah, Al, Bh2, Bl2, G);
            Gp = G;
        }
        gru_update<<<gruGrid, 256>>>(M2, b2, e2_bhh, C2, Gp, pa, pb, h, Ah, Al);
    }

    // ---- decoder ----
    for (int k = 0; k < NPRED; k++) {
        const float *pa, *pb;
        if (k == 0)      { pa = observed + (size_t)7 * ND; pb = observed + (size_t)6 * ND; }
        else if (k == 1) { pa = pred_out;                  pb = observed + (size_t)7 * ND; }
        else             { pa = pred_out + (size_t)(k-1)*ND; pb = pred_out + (size_t)(k-2)*ND; }
        gemm_tc<<<gemmGrid, 256, GEMM_SMEM>>>(tAh, tAl, tBdh, tBdl, Ah, Al, Bhd, Bld, G);
        gru_update<<<gruGrid, 256>>>(Md, bd, dec_bhh, nullptr, G, pa, pb, h, Ah, Al);
        h2n_pos<<<NB / 8, 256>>>(h, h2n_W, h2n_b, mix_W, mix_b, pa,
                                 rel_out + (size_t)k * NB * 5,
                                 pred_out + (size_t)k * ND);
    }
}